// round 15
// baseline (speedup 1.0000x reference)
#include <cuda_runtime.h>

#define NB     8
#define NATOM  512
#define NFEAT  42
#define NNEIGH 100
#define NPT    256
#define NH1    64
#define NH2    32

#define FT     384            // force kernel threads (divisible by 3!)
#define NPAIR  (NNEIGH*NFEAT) // 4200
#define NQ     (NPAIR*3/4)    // 3150 float4s per atom tile

// scratch for dE (input gradient), computed by ei_kernel, consumed by force_kernel
__device__ float g_dE[NB * NATOM * NFEAT];

// fast tanh: clamped exp-based, well within 1e-3 rel-err budget
__device__ __forceinline__ float fast_tanh(float x)
{
    x = fminf(15.0f, fmaxf(-15.0f, x));
    const float e = __expf(2.0f * x);
    return __fdividef(e - 1.0f, e + 1.0f);
}

// ---------------------------------------------------------------------------
// Kernel 1: per-atom MLP forward + backward, TWO atoms per warp.
// Grid: 256 blocks x 256 threads = 8 warps/block, 16 atoms/block.
// ---------------------------------------------------------------------------
__global__ __launch_bounds__(256) void ei_kernel(
    const float* __restrict__ image,
    const float* __restrict__ W0, const float* __restrict__ b0,
    const float* __restrict__ W1, const float* __restrict__ b1,
    const float* __restrict__ W2, const float* __restrict__ b2,
    float* __restrict__ out)
{
    __shared__ float sW0[NH1 * 43];
    __shared__ float sW1[NH2 * 65];
    __shared__ float sW2[NH2];
    __shared__ float sb0[NH1];
    __shared__ float sb1[NH2];
    __shared__ float sb2v;
    __shared__ float sx [16][NFEAT];
    __shared__ float sh1[16][NH1];
    __shared__ float sg2[16][NH2];
    __shared__ float sg1[16][NH1];

    const int tid = threadIdx.x;
    const int w   = tid >> 5;        // warp id: atoms w and w+8
    const int l   = tid & 31;

    const int base = blockIdx.x * 16;        // never crosses the type boundary
    const int b    = base / NATOM;
    const int a0   = base % NATOM;
    const int t    = a0 / NPT;

    for (int i = tid; i < NH1 * NFEAT; i += 256) {
        int r = i / NFEAT, c = i - r * NFEAT;
        sW0[r * 43 + c] = W0[t * NH1 * NFEAT + i];
    }
    for (int i = tid; i < NH2 * NH1; i += 256) {
        int r = i >> 6, c = i & 63;
        sW1[r * 65 + c] = W1[t * NH2 * NH1 + i];
    }
    if (tid < NH2) sW2[tid] = W2[t * NH2 + tid];
    if (tid < NH1) sb0[tid] = b0[t * NH1 + tid];
    if (tid < NH2) sb1[tid] = b1[t * NH2 + tid];
    if (tid == 0)  sb2v = b2[t];
    __syncthreads();

    const int gA = b * NATOM + (a0 + w);          // atom A
    const int gB = gA + 8;                        // atom B
    const int wB = w + 8;

    if (l < NFEAT) {
        sx[w][l]  = image[gA * NFEAT + l];
        sx[wB][l] = image[gB * NFEAT + l];
    }
    if (l < NFEAT - 32) {
        sx[w][32 + l]  = image[gA * NFEAT + 32 + l];
        sx[wB][32 + l] = image[gB * NFEAT + 32 + l];
    }
    __syncwarp();

    float s1a = sb0[l], s2a = sb0[32 + l];
    float s1b = s1a,    s2b = s2a;
    #pragma unroll
    for (int f = 0; f < NFEAT; f++) {
        const float w0a = sW0[l * 43 + f];
        const float w0b = sW0[(32 + l) * 43 + f];
        const float xa  = sx[w][f];
        const float xb  = sx[wB][f];
        s1a += xa * w0a;  s2a += xa * w0b;
        s1b += xb * w0a;  s2b += xb * w0b;
    }
    const float h1aA = fast_tanh(s1a), h1bA = fast_tanh(s2a);
    const float h1aB = fast_tanh(s1b), h1bB = fast_tanh(s2b);
    sh1[w][l]  = h1aA; sh1[w][32 + l]  = h1bA;
    sh1[wB][l] = h1aB; sh1[wB][32 + l] = h1bB;
    __syncwarp();

    float sA = sb1[l], sB = sb1[l];
    #pragma unroll
    for (int i = 0; i < NH1; i++) {
        const float w1 = sW1[l * 65 + i];
        sA += sh1[w][i]  * w1;
        sB += sh1[wB][i] * w1;
    }
    const float h2A = fast_tanh(sA), h2B = fast_tanh(sB);
    const float w2v = sW2[l];
    sg2[w][l]  = w2v * (1.0f - h2A * h2A);
    sg2[wB][l] = w2v * (1.0f - h2B * h2B);

    float vA = h2A * w2v, vB = h2B * w2v;
    #pragma unroll
    for (int o = 16; o > 0; o >>= 1) {
        vA += __shfl_down_sync(0xffffffffu, vA, o);
        vB += __shfl_down_sync(0xffffffffu, vB, o);
    }
    if (l == 0) { out[8 + gA] = vA + sb2v; out[8 + gB] = vB + sb2v; }
    __syncwarp();

    float t1a = 0.0f, t2a = 0.0f, t1b = 0.0f, t2b = 0.0f;
    #pragma unroll
    for (int j = 0; j < NH2; j++) {
        const float w1a = sW1[j * 65 + l];
        const float w1b = sW1[j * 65 + 32 + l];
        const float ga  = sg2[w][j];
        const float gb  = sg2[wB][j];
        t1a += ga * w1a;  t2a += ga * w1b;
        t1b += gb * w1a;  t2b += gb * w1b;
    }
    sg1[w][l]       = t1a * (1.0f - h1aA * h1aA);
    sg1[w][32 + l]  = t2a * (1.0f - h1bA * h1bA);
    sg1[wB][l]      = t1b * (1.0f - h1aB * h1aB);
    sg1[wB][32 + l] = t2b * (1.0f - h1bB * h1bB);
    __syncwarp();

    const int c2 = (l < NFEAT - 32) ? (32 + l) : 0;
    float d1a = 0.0f, d2a = 0.0f, d1b = 0.0f, d2b = 0.0f;
    #pragma unroll
    for (int i = 0; i < NH1; i++) {
        const float w0a = sW0[i * 43 + l];
        const float w0b = sW0[i * 43 + c2];
        const float ga  = sg1[w][i];
        const float gb  = sg1[wB][i];
        d1a += ga * w0a;  d2a += ga * w0b;
        d1b += gb * w0a;  d2b += gb * w0b;
    }
    if (l < NFEAT) {
        g_dE[gA * NFEAT + l] = d1a;
        g_dE[gB * NFEAT + l] = d1b;
    }
    if (l < NFEAT - 32) {
        g_dE[gA * NFEAT + 32 + l] = d2a;
        g_dE[gB * NFEAT + 32 + l] = d2b;
    }
}

// ---------------------------------------------------------------------------
// Kernel 2: Force. 4096 blocks x 384 threads (384 % 3 == 0 is load-bearing).
// R12 loop + depth-3 rotating register pipeline on the dfeat stream so each
// thread keeps ~3 LDG.128 continuously in flight (R12's 32-reg build capped
// MLP at ~2, pinning DRAM at 58%). __launch_bounds__(384,4) gives ptxas a
// ~42-reg budget -> 4 blocks/SM (48 warps, 75% occ), outstanding bytes/SM
// ~18-24KB >= the ~17.7KB needed to saturate HBM.
// Multiplier fetch: 2 LDS.32 + 2 data SELs (o0=0, o3=1 always).
// Blocks 0..7 also fold in the Etot reduction (deterministic order).
// ---------------------------------------------------------------------------
__global__ __launch_bounds__(FT, 4) void force_kernel(
    const float* __restrict__ dfeat,
    const int* __restrict__ neighbor,
    float* __restrict__ out)
{
    __shared__ float sg[NPAIR];          // 4200 gathered dE values
    __shared__ int   sn[NNEIGH];
    __shared__ float red[FT / 32][3];
    __shared__ float sred[8];

    const int tid  = threadIdx.x;
    const int gidx = blockIdx.x;             // b*NATOM + a
    const int b    = gidx >> 9;

    if (tid < NNEIGH)
        sn[tid] = neighbor[gidx * NNEIGH + tid];

    // fused Etot partial (blocks 0..7, first 256 threads): deterministic
    if (gidx < NB && tid < 256) {
        const float* Ei = out + 8 + gidx * NATOM;
        float v = Ei[tid] + Ei[tid + 256];
        #pragma unroll
        for (int o = 16; o > 0; o >>= 1) v += __shfl_down_sync(0xffffffffu, v, o);
        if ((tid & 31) == 0) sred[tid >> 5] = v;
    }
    __syncthreads();

    // Gather: one L2 load per (n,f) pair; index 0 -> zero pad row
    for (int p = tid; p < NPAIR; p += FT) {
        const int n = p / NFEAT;
        const int f = p - n * NFEAT;
        const int j = sn[n];
        sg[p] = j ? g_dE[(b * NATOM + (j - 1)) * NFEAT + f] : 0.0f;
    }
    __syncthreads();

    if (gidx < NB && tid == 0) {
        float s = 0.0f;
        #pragma unroll
        for (int ww = 0; ww < 8; ww++) s += sred[ww];
        out[gidx] = s;
    }

    const float4* __restrict__ df = (const float4*)(dfeat + (long)gidx * (NPAIR * 3));

    const int  phase = tid % 3;              // == q mod 3 for all iterations
    const int  m0    = (4 * tid) / 3;
    const bool s1hi  = (phase == 2);         // slot1 uses gB iff phase==2
    const bool s2hi  = (phase >= 1);         // slot2 uses gB iff phase>=1
    const bool tail_ok = tid < (NQ - 8 * FT);   // 78 tail threads

    float a0 = 0.0f, a1 = 0.0f, a2 = 0.0f, a3 = 0.0f;

    // depth-3 rotating pipeline: slots refilled as consumed -> ~3 LDG.128
    // continuously in flight per thread.
    float4 vbuf[3];
    vbuf[0] = df[tid];
    vbuf[1] = df[tid + FT];
    vbuf[2] = df[tid + 2 * FT];

    #pragma unroll
    for (int it = 0; it < 8; it++) {
        const float4 v = vbuf[it % 3];
        const int nq = it + 3;
        if (nq < 8) {
            vbuf[it % 3] = df[tid + nq * FT];
        } else if (nq == 8) {
            if (tail_ok) vbuf[2] = df[tid + 8 * FT];
        }
        const int m = m0 + it * 512;
        const float gA = sg[m];
        const float gB = sg[m + 1];
        a0 += gA * v.x;
        a1 += (s1hi ? gB : gA) * v.y;
        a2 += (s2hi ? gB : gA) * v.z;
        a3 += gB * v.w;
    }
    // tail: it = 8 (vbuf[2] was conditionally refilled at it==5)
    if (tail_ok) {
        const float4 v = vbuf[2];
        const int m = m0 + 8 * 512;           // m0 max 102 -> 4198+1 < 4200
        const float gA = sg[m];
        const float gB = sg[m + 1];
        a0 += gA * v.x;
        a1 += (s1hi ? gB : gA) * v.y;
        a2 += (s2hi ? gB : gA) * v.z;
        a3 += gB * v.w;
    }

    // map slot accumulators to (x,y,z):  k(s) = (phase + s) mod 3
    float ax, ay, az;
    if (phase == 0)      { ax = a0 + a3; ay = a1;      az = a2;      }
    else if (phase == 1) { ax = a2;      ay = a0 + a3; az = a1;      }
    else                 { ax = a1;      ay = a2;      az = a0 + a3; }

    #pragma unroll
    for (int o = 16; o > 0; o >>= 1) {
        ax += __shfl_down_sync(0xffffffffu, ax, o);
        ay += __shfl_down_sync(0xffffffffu, ay, o);
        az += __shfl_down_sync(0xffffffffu, az, o);
    }
    const int w = tid >> 5, l = tid & 31;
    if (l == 0) { red[w][0] = ax; red[w][1] = ay; red[w][2] = az; }
    __syncthreads();
    if (tid < 3) {
        float s = 0.0f;
        #pragma unroll
        for (int ww = 0; ww < FT / 32; ww++) s += red[ww][tid];
        out[8 + NB * NATOM + gidx * 3 + tid] = s;
    }
}

// ---------------------------------------------------------------------------
// Launch: out layout = [Etot(8) | Ei(4096) | Force(12288)] = 16392 f32
// ---------------------------------------------------------------------------
extern "C" void kernel_launch(void* const* d_in, const int* in_sizes, int n_in,
                              void* d_out, int out_size)
{
    const float* image    = (const float*)d_in[0];
    const float* dfeat    = (const float*)d_in[1];
    const int*   neighbor = (const int*)d_in[2];
    // d_in[3] = natoms_img (unused)
    const float* W0 = (const float*)d_in[4];
    const float* b0 = (const float*)d_in[5];
    const float* W1 = (const float*)d_in[6];
    const float* b1 = (const float*)d_in[7];
    const float* W2 = (const float*)d_in[8];
    const float* b2 = (const float*)d_in[9];
    float* out = (float*)d_out;

    ei_kernel<<<(NB * NATOM) / 16, 256>>>(image, W0, b0, W1, b1, W2, b2, out);
    force_kernel<<<NB * NATOM, FT>>>(dfeat, neighbor, out);
}

// round 16
// speedup vs baseline: 1.1028x; 1.1028x over previous
#include <cuda_runtime.h>
#include <cstdint>

#define NB     8
#define NATOM  512
#define NFEAT  42
#define NNEIGH 100
#define NPT    256
#define NH1    64
#define NH2    32

#define FT     384            // force kernel threads (divisible by 3!)
#define NPAIR  (NNEIGH*NFEAT) // 4200
#define NQ     (NPAIR*3/4)    // 3150 float4s per atom tile
#define NROW   (NATOM + 1)    // padded rows per batch (row 0 = zeros)

// padded dE scratch: row r = b*NROW + j ; j==0 is a zero row, j>=1 -> atom j-1
__device__ float g_dE[NB * NROW * NFEAT];

__device__ __forceinline__ void cp_async4(uint32_t smem_addr, const void* gptr)
{
    asm volatile("cp.async.ca.shared.global [%0], [%1], 4;"
                 :: "r"(smem_addr), "l"(gptr) : "memory");
}
__device__ __forceinline__ void cp_async_commit()
{
    asm volatile("cp.async.commit_group;" ::: "memory");
}
template<int N> __device__ __forceinline__ void cp_async_wait()
{
    asm volatile("cp.async.wait_group %0;" :: "n"(N) : "memory");
}

// fast tanh: clamped exp-based, well within 1e-3 rel-err budget
__device__ __forceinline__ float fast_tanh(float x)
{
    x = fminf(15.0f, fmaxf(-15.0f, x));
    const float e = __expf(2.0f * x);
    return __fdividef(e - 1.0f, e + 1.0f);
}

// ---------------------------------------------------------------------------
// Kernel 1: per-atom MLP forward + backward, TWO atoms per warp.
// Grid: 256 blocks x 256 threads = 8 warps/block, 16 atoms/block.
// Also zeroes the per-batch zero-row of the padded g_dE (blocks 0..7).
// ---------------------------------------------------------------------------
__global__ __launch_bounds__(256) void ei_kernel(
    const float* __restrict__ image,
    const float* __restrict__ W0, const float* __restrict__ b0,
    const float* __restrict__ W1, const float* __restrict__ b1,
    const float* __restrict__ W2, const float* __restrict__ b2,
    float* __restrict__ out)
{
    __shared__ float sW0[NH1 * 43];
    __shared__ float sW1[NH2 * 65];
    __shared__ float sW2[NH2];
    __shared__ float sb0[NH1];
    __shared__ float sb1[NH2];
    __shared__ float sb2v;
    __shared__ float sx [16][NFEAT];
    __shared__ float sh1[16][NH1];
    __shared__ float sg2[16][NH2];
    __shared__ float sg1[16][NH1];

    const int tid = threadIdx.x;
    const int w   = tid >> 5;        // warp id: atoms w and w+8
    const int l   = tid & 31;

    const int base = blockIdx.x * 16;        // never crosses the type boundary
    const int b    = base / NATOM;
    const int a0   = base % NATOM;
    const int t    = a0 / NPT;

    // zero-row init for the padded gather layout (one row per batch)
    if (blockIdx.x < NB && tid < NFEAT)
        g_dE[blockIdx.x * NROW * NFEAT + tid] = 0.0f;

    for (int i = tid; i < NH1 * NFEAT; i += 256) {
        int r = i / NFEAT, c = i - r * NFEAT;
        sW0[r * 43 + c] = W0[t * NH1 * NFEAT + i];
    }
    for (int i = tid; i < NH2 * NH1; i += 256) {
        int r = i >> 6, c = i & 63;
        sW1[r * 65 + c] = W1[t * NH2 * NH1 + i];
    }
    if (tid < NH2) sW2[tid] = W2[t * NH2 + tid];
    if (tid < NH1) sb0[tid] = b0[t * NH1 + tid];
    if (tid < NH2) sb1[tid] = b1[t * NH2 + tid];
    if (tid == 0)  sb2v = b2[t];
    __syncthreads();

    const int gA = b * NATOM + (a0 + w);          // atom A (global)
    const int gB = gA + 8;                        // atom B
    const int wB = w + 8;
    const long rowA = (long)(gA + b + 1) * NFEAT; // padded row offsets
    const long rowB = (long)(gB + b + 1) * NFEAT;

    if (l < NFEAT) {
        sx[w][l]  = image[gA * NFEAT + l];
        sx[wB][l] = image[gB * NFEAT + l];
    }
    if (l < NFEAT - 32) {
        sx[w][32 + l]  = image[gA * NFEAT + 32 + l];
        sx[wB][32 + l] = image[gB * NFEAT + 32 + l];
    }
    __syncwarp();

    float s1a = sb0[l], s2a = sb0[32 + l];
    float s1b = s1a,    s2b = s2a;
    #pragma unroll
    for (int f = 0; f < NFEAT; f++) {
        const float w0a = sW0[l * 43 + f];
        const float w0b = sW0[(32 + l) * 43 + f];
        const float xa  = sx[w][f];
        const float xb  = sx[wB][f];
        s1a += xa * w0a;  s2a += xa * w0b;
        s1b += xb * w0a;  s2b += xb * w0b;
    }
    const float h1aA = fast_tanh(s1a), h1bA = fast_tanh(s2a);
    const float h1aB = fast_tanh(s1b), h1bB = fast_tanh(s2b);
    sh1[w][l]  = h1aA; sh1[w][32 + l]  = h1bA;
    sh1[wB][l] = h1aB; sh1[wB][32 + l] = h1bB;
    __syncwarp();

    float sA = sb1[l], sB = sb1[l];
    #pragma unroll
    for (int i = 0; i < NH1; i++) {
        const float w1 = sW1[l * 65 + i];
        sA += sh1[w][i]  * w1;
        sB += sh1[wB][i] * w1;
    }
    const float h2A = fast_tanh(sA), h2B = fast_tanh(sB);
    const float w2v = sW2[l];
    sg2[w][l]  = w2v * (1.0f - h2A * h2A);
    sg2[wB][l] = w2v * (1.0f - h2B * h2B);

    float vA = h2A * w2v, vB = h2B * w2v;
    #pragma unroll
    for (int o = 16; o > 0; o >>= 1) {
        vA += __shfl_down_sync(0xffffffffu, vA, o);
        vB += __shfl_down_sync(0xffffffffu, vB, o);
    }
    if (l == 0) { out[8 + gA] = vA + sb2v; out[8 + gB] = vB + sb2v; }
    __syncwarp();

    float t1a = 0.0f, t2a = 0.0f, t1b = 0.0f, t2b = 0.0f;
    #pragma unroll
    for (int j = 0; j < NH2; j++) {
        const float w1a = sW1[j * 65 + l];
        const float w1b = sW1[j * 65 + 32 + l];
        const float ga  = sg2[w][j];
        const float gb  = sg2[wB][j];
        t1a += ga * w1a;  t2a += ga * w1b;
        t1b += gb * w1a;  t2b += gb * w1b;
    }
    sg1[w][l]       = t1a * (1.0f - h1aA * h1aA);
    sg1[w][32 + l]  = t2a * (1.0f - h1bA * h1bA);
    sg1[wB][l]      = t1b * (1.0f - h1aB * h1aB);
    sg1[wB][32 + l] = t2b * (1.0f - h1bB * h1bB);
    __syncwarp();

    const int c2 = (l < NFEAT - 32) ? (32 + l) : 0;
    float d1a = 0.0f, d2a = 0.0f, d1b = 0.0f, d2b = 0.0f;
    #pragma unroll
    for (int i = 0; i < NH1; i++) {
        const float w0a = sW0[i * 43 + l];
        const float w0b = sW0[i * 43 + c2];
        const float ga  = sg1[w][i];
        const float gb  = sg1[wB][i];
        d1a += ga * w0a;  d2a += ga * w0b;
        d1b += gb * w0a;  d2b += gb * w0b;
    }
    if (l < NFEAT) {
        g_dE[rowA + l] = d1a;
        g_dE[rowB + l] = d1b;
    }
    if (l < NFEAT - 32) {
        g_dE[rowA + 32 + l] = d2a;
        g_dE[rowB + 32 + l] = d2b;
    }
}

// one atom's stream + reduction + output (uniform; contains one barrier)
__device__ __forceinline__ void stream_atom(
    const float4* __restrict__ df, const float* __restrict__ sg,
    int tid, int m0, int phase, bool s1hi, bool s2hi, bool tail_ok,
    float (*red)[3], float* __restrict__ outp)
{
    float a0 = 0.0f, a1 = 0.0f, a2 = 0.0f, a3 = 0.0f;
    #pragma unroll
    for (int it = 0; it < 8; it++) {
        const float4 v = df[tid + it * FT];
        const int m = m0 + it * 512;
        const float gA = sg[m];
        const float gB = sg[m + 1];
        a0 += gA * v.x;
        a1 += (s1hi ? gB : gA) * v.y;
        a2 += (s2hi ? gB : gA) * v.z;
        a3 += gB * v.w;
    }
    if (tail_ok) {
        const float4 v = df[tid + 8 * FT];
        const int m = m0 + 8 * 512;           // m0 max 102 -> 4198+1 < 4200
        const float gA = sg[m];
        const float gB = sg[m + 1];
        a0 += gA * v.x;
        a1 += (s1hi ? gB : gA) * v.y;
        a2 += (s2hi ? gB : gA) * v.z;
        a3 += gB * v.w;
    }

    float ax, ay, az;                        // k(s) = (phase + s) mod 3
    if (phase == 0)      { ax = a0 + a3; ay = a1;      az = a2;      }
    else if (phase == 1) { ax = a2;      ay = a0 + a3; az = a1;      }
    else                 { ax = a1;      ay = a2;      az = a0 + a3; }

    #pragma unroll
    for (int o = 16; o > 0; o >>= 1) {
        ax += __shfl_down_sync(0xffffffffu, ax, o);
        ay += __shfl_down_sync(0xffffffffu, ay, o);
        az += __shfl_down_sync(0xffffffffu, az, o);
    }
    const int w = tid >> 5, l = tid & 31;
    if (l == 0) { red[w][0] = ax; red[w][1] = ay; red[w][2] = az; }
    __syncthreads();
    if (tid < 3) {
        float s = 0.0f;
        #pragma unroll
        for (int ww = 0; ww < FT / 32; ww++) s += red[ww][tid];
        outp[tid] = s;
    }
}

// ---------------------------------------------------------------------------
// Kernel 2: Force. 2048 blocks x 384 threads, TWO atoms per block with
// double-buffered cp.async gather: gather(1) runs in the LSU background
// while atom 0 streams, so the L2-gather bubble is off the DRAM critical
// path for half the atoms. Gather is branch-free via the padded zero row.
// Blocks 0..3 also fold in the Etot reduction (deterministic order).
// ---------------------------------------------------------------------------
__global__ __launch_bounds__(FT, 5) void force_kernel(
    const float* __restrict__ dfeat,
    const int* __restrict__ neighbor,
    float* __restrict__ out)
{
    __shared__ float sg[2][NPAIR];       // 2 x 4200 gathered dE values
    __shared__ int   sn[2][NNEIGH];
    __shared__ float red[FT / 32][3];
    __shared__ float sred[2][8];

    const int tid = threadIdx.x;
    const int g0  = blockIdx.x * 2;          // b*NATOM + a  (even atom)
    const int g1  = g0 + 1;
    const int b   = g0 >> 9;
    const float* __restrict__ dErows = g_dE + (long)b * NROW * NFEAT;

    if (tid < NNEIGH)
        sn[0][tid] = neighbor[g0 * NNEIGH + tid];
    else if (tid < 2 * NNEIGH)
        sn[1][tid - NNEIGH] = neighbor[g1 * NNEIGH + tid - NNEIGH];
    __syncthreads();

    // gather both atoms via cp.async (4B, branch-free: j==0 hits zero row)
    const uint32_t sg0a = (uint32_t)__cvta_generic_to_shared(&sg[0][0]);
    const uint32_t sg1a = (uint32_t)__cvta_generic_to_shared(&sg[1][0]);
    for (int p = tid; p < NPAIR; p += FT) {
        const int n = p / NFEAT;
        const int f = p - n * NFEAT;
        cp_async4(sg0a + 4u * p, dErows + sn[0][n] * NFEAT + f);
    }
    cp_async_commit();
    for (int p = tid; p < NPAIR; p += FT) {
        const int n = p / NFEAT;
        const int f = p - n * NFEAT;
        cp_async4(sg1a + 4u * p, dErows + sn[1][n] * NFEAT + f);
    }
    cp_async_commit();

    // Etot partials (blocks 0..3 -> batches g0, g1 < 8), deterministic
    if (g0 < NB && tid < 256) {
        const float* Ei0 = out + 8 + g0 * NATOM;
        const float* Ei1 = out + 8 + g1 * NATOM;
        float v0 = Ei0[tid] + Ei0[tid + 256];
        float v1 = Ei1[tid] + Ei1[tid + 256];
        #pragma unroll
        for (int o = 16; o > 0; o >>= 1) {
            v0 += __shfl_down_sync(0xffffffffu, v0, o);
            v1 += __shfl_down_sync(0xffffffffu, v1, o);
        }
        if ((tid & 31) == 0) { sred[0][tid >> 5] = v0; sred[1][tid >> 5] = v1; }
    }

    const int  phase = tid % 3;
    const int  m0    = (4 * tid) / 3;
    const bool s1hi  = (phase == 2);
    const bool s2hi  = (phase >= 1);
    const bool tail_ok = tid < (NQ - 8 * FT);

    cp_async_wait<1>();                  // sg[0] landed (sg[1] may be pending)
    __syncthreads();

    if (g0 < NB && tid == 0) {
        float s0 = 0.0f, s1 = 0.0f;
        #pragma unroll
        for (int ww = 0; ww < 8; ww++) { s0 += sred[0][ww]; s1 += sred[1][ww]; }
        out[g0] = s0; out[g1] = s1;
    }

    const float4* __restrict__ df0 = (const float4*)(dfeat + (long)g0 * (NPAIR * 3));
    stream_atom(df0, sg[0], tid, m0, phase, s1hi, s2hi, tail_ok, red,
                out + 8 + NB * NATOM + g0 * 3);

    cp_async_wait<0>();                  // sg[1] landed (overlapped atom 0)
    __syncthreads();

    const float4* __restrict__ df1 = (const float4*)(dfeat + (long)g1 * (NPAIR * 3));
    stream_atom(df1, sg[1], tid, m0, phase, s1hi, s2hi, tail_ok, red,
                out + 8 + NB * NATOM + g1 * 3);
}

// ---------------------------------------------------------------------------
// Launch: out layout = [Etot(8) | Ei(4096) | Force(12288)] = 16392 f32
// ---------------------------------------------------------------------------
extern "C" void kernel_launch(void* const* d_in, const int* in_sizes, int n_in,
                              void* d_out, int out_size)
{
    const float* image    = (const float*)d_in[0];
    const float* dfeat    = (const float*)d_in[1];
    const int*   neighbor = (const int*)d_in[2];
    // d_in[3] = natoms_img (unused)
    const float* W0 = (const float*)d_in[4];
    const float* b0 = (const float*)d_in[5];
    const float* W1 = (const float*)d_in[6];
    const float* b1 = (const float*)d_in[7];
    const float* W2 = (const float*)d_in[8];
    const float* b2 = (const float*)d_in[9];
    float* out = (float*)d_out;

    ei_kernel<<<(NB * NATOM) / 16, 256>>>(image, W0, b0, W1, b1, W2, b2, out);
    force_kernel<<<(NB * NATOM) / 2, FT>>>(dfeat, neighbor, out);
}

// round 17
// speedup vs baseline: 1.1404x; 1.0341x over previous
#include <cuda_runtime.h>
#include <cstdint>

#define NB     8
#define NATOM  512
#define NFEAT  42
#define NNEIGH 100
#define NPT    256
#define NH1    64
#define NH2    32

#define FT     384            // force kernel threads (divisible by 3!)
#define NPAIR  (NNEIGH*NFEAT) // 4200
#define NP2    (NPAIR/2)      // 2100 8-byte gather pairs
#define NQ     (NPAIR*3/4)    // 3150 float4s per atom tile
#define NROW   (NATOM + 1)    // padded rows per batch (row 0 = zeros)

// padded dE scratch: row r = b*NROW + j ; j==0 is a zero row, j>=1 -> atom j-1
__device__ float g_dE[NB * NROW * NFEAT];

__device__ __forceinline__ void cp_async8(uint32_t smem_addr, const void* gptr)
{
    asm volatile("cp.async.ca.shared.global [%0], [%1], 8;"
                 :: "r"(smem_addr), "l"(gptr) : "memory");
}
__device__ __forceinline__ void cp_async_commit()
{
    asm volatile("cp.async.commit_group;" ::: "memory");
}
template<int N> __device__ __forceinline__ void cp_async_wait()
{
    asm volatile("cp.async.wait_group %0;" :: "n"(N) : "memory");
}

// fast tanh: clamped exp-based, well within 1e-3 rel-err budget
__device__ __forceinline__ float fast_tanh(float x)
{
    x = fminf(15.0f, fmaxf(-15.0f, x));
    const float e = __expf(2.0f * x);
    return __fdividef(e - 1.0f, e + 1.0f);
}

// ---------------------------------------------------------------------------
// Kernel 1: per-atom MLP forward + backward, TWO atoms per warp.
// Grid: 256 blocks x 256 threads = 8 warps/block, 16 atoms/block.
// Also zeroes the per-batch zero-row of the padded g_dE (blocks 0..7).
// ---------------------------------------------------------------------------
__global__ __launch_bounds__(256) void ei_kernel(
    const float* __restrict__ image,
    const float* __restrict__ W0, const float* __restrict__ b0,
    const float* __restrict__ W1, const float* __restrict__ b1,
    const float* __restrict__ W2, const float* __restrict__ b2,
    float* __restrict__ out)
{
    __shared__ float sW0[NH1 * 43];
    __shared__ float sW1[NH2 * 65];
    __shared__ float sW2[NH2];
    __shared__ float sb0[NH1];
    __shared__ float sb1[NH2];
    __shared__ float sb2v;
    __shared__ float sx [16][NFEAT];
    __shared__ float sh1[16][NH1];
    __shared__ float sg2[16][NH2];
    __shared__ float sg1[16][NH1];

    const int tid = threadIdx.x;
    const int w   = tid >> 5;        // warp id: atoms w and w+8
    const int l   = tid & 31;

    const int base = blockIdx.x * 16;        // never crosses the type boundary
    const int b    = base / NATOM;
    const int a0   = base % NATOM;
    const int t    = a0 / NPT;

    // zero-row init for the padded gather layout (one row per batch)
    if (blockIdx.x < NB && tid < NFEAT)
        g_dE[blockIdx.x * NROW * NFEAT + tid] = 0.0f;

    for (int i = tid; i < NH1 * NFEAT; i += 256) {
        int r = i / NFEAT, c = i - r * NFEAT;
        sW0[r * 43 + c] = W0[t * NH1 * NFEAT + i];
    }
    for (int i = tid; i < NH2 * NH1; i += 256) {
        int r = i >> 6, c = i & 63;
        sW1[r * 65 + c] = W1[t * NH2 * NH1 + i];
    }
    if (tid < NH2) sW2[tid] = W2[t * NH2 + tid];
    if (tid < NH1) sb0[tid] = b0[t * NH1 + tid];
    if (tid < NH2) sb1[tid] = b1[t * NH2 + tid];
    if (tid == 0)  sb2v = b2[t];
    __syncthreads();

    const int gA = b * NATOM + (a0 + w);          // atom A (global)
    const int gB = gA + 8;                        // atom B
    const int wB = w + 8;
    const long rowA = (long)(gA + b + 1) * NFEAT; // padded row offsets
    const long rowB = (long)(gB + b + 1) * NFEAT;

    if (l < NFEAT) {
        sx[w][l]  = image[gA * NFEAT + l];
        sx[wB][l] = image[gB * NFEAT + l];
    }
    if (l < NFEAT - 32) {
        sx[w][32 + l]  = image[gA * NFEAT + 32 + l];
        sx[wB][32 + l] = image[gB * NFEAT + 32 + l];
    }
    __syncwarp();

    float s1a = sb0[l], s2a = sb0[32 + l];
    float s1b = s1a,    s2b = s2a;
    #pragma unroll
    for (int f = 0; f < NFEAT; f++) {
        const float w0a = sW0[l * 43 + f];
        const float w0b = sW0[(32 + l) * 43 + f];
        const float xa  = sx[w][f];
        const float xb  = sx[wB][f];
        s1a += xa * w0a;  s2a += xa * w0b;
        s1b += xb * w0a;  s2b += xb * w0b;
    }
    const float h1aA = fast_tanh(s1a), h1bA = fast_tanh(s2a);
    const float h1aB = fast_tanh(s1b), h1bB = fast_tanh(s2b);
    sh1[w][l]  = h1aA; sh1[w][32 + l]  = h1bA;
    sh1[wB][l] = h1aB; sh1[wB][32 + l] = h1bB;
    __syncwarp();

    float sA = sb1[l], sB = sb1[l];
    #pragma unroll
    for (int i = 0; i < NH1; i++) {
        const float w1 = sW1[l * 65 + i];
        sA += sh1[w][i]  * w1;
        sB += sh1[wB][i] * w1;
    }
    const float h2A = fast_tanh(sA), h2B = fast_tanh(sB);
    const float w2v = sW2[l];
    sg2[w][l]  = w2v * (1.0f - h2A * h2A);
    sg2[wB][l] = w2v * (1.0f - h2B * h2B);

    float vA = h2A * w2v, vB = h2B * w2v;
    #pragma unroll
    for (int o = 16; o > 0; o >>= 1) {
        vA += __shfl_down_sync(0xffffffffu, vA, o);
        vB += __shfl_down_sync(0xffffffffu, vB, o);
    }
    if (l == 0) { out[8 + gA] = vA + sb2v; out[8 + gB] = vB + sb2v; }
    __syncwarp();

    float t1a = 0.0f, t2a = 0.0f, t1b = 0.0f, t2b = 0.0f;
    #pragma unroll
    for (int j = 0; j < NH2; j++) {
        const float w1a = sW1[j * 65 + l];
        const float w1b = sW1[j * 65 + 32 + l];
        const float ga  = sg2[w][j];
        const float gb  = sg2[wB][j];
        t1a += ga * w1a;  t2a += ga * w1b;
        t1b += gb * w1a;  t2b += gb * w1b;
    }
    sg1[w][l]       = t1a * (1.0f - h1aA * h1aA);
    sg1[w][32 + l]  = t2a * (1.0f - h1bA * h1bA);
    sg1[wB][l]      = t1b * (1.0f - h1aB * h1aB);
    sg1[wB][32 + l] = t2b * (1.0f - h1bB * h1bB);
    __syncwarp();

    const int c2 = (l < NFEAT - 32) ? (32 + l) : 0;
    float d1a = 0.0f, d2a = 0.0f, d1b = 0.0f, d2b = 0.0f;
    #pragma unroll
    for (int i = 0; i < NH1; i++) {
        const float w0a = sW0[i * 43 + l];
        const float w0b = sW0[i * 43 + c2];
        const float ga  = sg1[w][i];
        const float gb  = sg1[wB][i];
        d1a += ga * w0a;  d2a += ga * w0b;
        d1b += gb * w0a;  d2b += gb * w0b;
    }
    if (l < NFEAT) {
        g_dE[rowA + l] = d1a;
        g_dE[rowB + l] = d1b;
    }
    if (l < NFEAT - 32) {
        g_dE[rowA + 32 + l] = d2a;
        g_dE[rowB + 32 + l] = d2b;
    }
}

// one atom's stream + reduction + output (uniform; contains one barrier)
__device__ __forceinline__ void stream_atom(
    const float4* __restrict__ df, const float* __restrict__ sg,
    int tid, int m0, int phase, bool s1hi, bool s2hi, bool tail_ok,
    float (*red)[3], float* __restrict__ outp)
{
    float a0 = 0.0f, a1 = 0.0f, a2 = 0.0f, a3 = 0.0f;
    #pragma unroll
    for (int it = 0; it < 8; it++) {
        const float4 v = df[tid + it * FT];
        const int m = m0 + it * 512;
        const float gA = sg[m];
        const float gB = sg[m + 1];
        a0 += gA * v.x;
        a1 += (s1hi ? gB : gA) * v.y;
        a2 += (s2hi ? gB : gA) * v.z;
        a3 += gB * v.w;
    }
    if (tail_ok) {
        const float4 v = df[tid + 8 * FT];
        const int m = m0 + 8 * 512;           // m0 max 102 -> 4198+1 < 4200
        const float gA = sg[m];
        const float gB = sg[m + 1];
        a0 += gA * v.x;
        a1 += (s1hi ? gB : gA) * v.y;
        a2 += (s2hi ? gB : gA) * v.z;
        a3 += gB * v.w;
    }

    float ax, ay, az;                        // k(s) = (phase + s) mod 3
    if (phase == 0)      { ax = a0 + a3; ay = a1;      az = a2;      }
    else if (phase == 1) { ax = a2;      ay = a0 + a3; az = a1;      }
    else                 { ax = a1;      ay = a2;      az = a0 + a3; }

    #pragma unroll
    for (int o = 16; o > 0; o >>= 1) {
        ax += __shfl_down_sync(0xffffffffu, ax, o);
        ay += __shfl_down_sync(0xffffffffu, ay, o);
        az += __shfl_down_sync(0xffffffffu, az, o);
    }
    const int w = tid >> 5, l = tid & 31;
    if (l == 0) { red[w][0] = ax; red[w][1] = ay; red[w][2] = az; }
    __syncthreads();
    if (tid < 3) {
        float s = 0.0f;
        #pragma unroll
        for (int ww = 0; ww < FT / 32; ww++) s += red[ww][tid];
        outp[tid] = s;
    }
}

// ---------------------------------------------------------------------------
// Kernel 2: Force. 2048 blocks x 384 threads, TWO atoms per block with
// double-buffered cp.async gather (gather(1) overlaps atom 0's stream).
// Gather now uses 8-BYTE cp.async: NFEAT=42 is even, so each dE row is
// exactly 21 aligned 8B pairs; with p2 = 21n + fp the smem dst is 8*p2 and
// the src (row stride 168B) is 8B-aligned. Halves gather op count (4200 vs
// 8400 per block) -> less LSU/L1 contention with the stream's LDGs and a
// shorter exposed first gather. Zero-row padding keeps it branch-free.
// Blocks 0..3 also fold in the Etot reduction (deterministic order).
// ---------------------------------------------------------------------------
__global__ __launch_bounds__(FT, 5) void force_kernel(
    const float* __restrict__ dfeat,
    const int* __restrict__ neighbor,
    float* __restrict__ out)
{
    __shared__ float sg[2][NPAIR];       // 2 x 4200 gathered dE values
    __shared__ int   sn[2][NNEIGH];
    __shared__ float red[FT / 32][3];
    __shared__ float sred[2][8];

    const int tid = threadIdx.x;
    const int g0  = blockIdx.x * 2;          // b*NATOM + a  (even atom)
    const int g1  = g0 + 1;
    const int b   = g0 >> 9;
    const float* __restrict__ dErows = g_dE + (long)b * NROW * NFEAT;

    if (tid < NNEIGH)
        sn[0][tid] = neighbor[g0 * NNEIGH + tid];
    else if (tid < 2 * NNEIGH)
        sn[1][tid - NNEIGH] = neighbor[g1 * NNEIGH + tid - NNEIGH];
    __syncthreads();

    // gather both atoms via 8B cp.async (branch-free: j==0 hits zero row)
    const uint32_t sg0a = (uint32_t)__cvta_generic_to_shared(&sg[0][0]);
    const uint32_t sg1a = (uint32_t)__cvta_generic_to_shared(&sg[1][0]);
    for (int p2 = tid; p2 < NP2; p2 += FT) {
        const int n  = p2 / 21;
        const int fp = p2 - n * 21;
        cp_async8(sg0a + 8u * p2, dErows + sn[0][n] * NFEAT + 2 * fp);
    }
    cp_async_commit();
    for (int p2 = tid; p2 < NP2; p2 += FT) {
        const int n  = p2 / 21;
        const int fp = p2 - n * 21;
        cp_async8(sg1a + 8u * p2, dErows + sn[1][n] * NFEAT + 2 * fp);
    }
    cp_async_commit();

    // Etot partials (blocks 0..3 -> batches g0, g1 < 8), deterministic
    if (g0 < NB && tid < 256) {
        const float* Ei0 = out + 8 + g0 * NATOM;
        const float* Ei1 = out + 8 + g1 * NATOM;
        float v0 = Ei0[tid] + Ei0[tid + 256];
        float v1 = Ei1[tid] + Ei1[tid + 256];
        #pragma unroll
        for (int o = 16; o > 0; o >>= 1) {
            v0 += __shfl_down_sync(0xffffffffu, v0, o);
            v1 += __shfl_down_sync(0xffffffffu, v1, o);
        }
        if ((tid & 31) == 0) { sred[0][tid >> 5] = v0; sred[1][tid >> 5] = v1; }
    }

    const int  phase = tid % 3;
    const int  m0    = (4 * tid) / 3;
    const bool s1hi  = (phase == 2);
    const bool s2hi  = (phase >= 1);
    const bool tail_ok = tid < (NQ - 8 * FT);

    cp_async_wait<1>();                  // sg[0] landed (sg[1] may be pending)
    __syncthreads();

    if (g0 < NB && tid == 0) {
        float s0 = 0.0f, s1 = 0.0f;
        #pragma unroll
        for (int ww = 0; ww < 8; ww++) { s0 += sred[0][ww]; s1 += sred[1][ww]; }
        out[g0] = s0; out[g1] = s1;
    }

    const float4* __restrict__ df0 = (const float4*)(dfeat + (long)g0 * (NPAIR * 3));
    stream_atom(df0, sg[0], tid, m0, phase, s1hi, s2hi, tail_ok, red,
                out + 8 + NB * NATOM + g0 * 3);

    cp_async_wait<0>();                  // sg[1] landed (overlapped atom 0)
    __syncthreads();

    const float4* __restrict__ df1 = (const float4*)(dfeat + (long)g1 * (NPAIR * 3));
    stream_atom(df1, sg[1], tid, m0, phase, s1hi, s2hi, tail_ok, red,
                out + 8 + NB * NATOM + g1 * 3);
}

// ---------------------------------------------------------------------------
// Launch: out layout = [Etot(8) | Ei(4096) | Force(12288)] = 16392 f32
// ---------------------------------------------------------------------------
extern "C" void kernel_launch(void* const* d_in, const int* in_sizes, int n_in,
                              void* d_out, int out_size)
{
    const float* image    = (const float*)d_in[0];
    const float* dfeat    = (const float*)d_in[1];
    const int*   neighbor = (const int*)d_in[2];
    // d_in[3] = natoms_img (unused)
    const float* W0 = (const float*)d_in[4];
    const float* b0 = (const float*)d_in[5];
    const float* W1 = (const float*)d_in[6];
    const float* b1 = (const float*)d_in[7];
    const float* W2 = (const float*)d_in[8];
    const float* b2 = (const float*)d_in[9];
    float* out = (float*)d_out;

    ei_kernel<<<(NB * NATOM) / 16, 256>>>(image, W0, b0, W1, b1, W2, b2, out);
    force_kernel<<<(NB * NATOM) / 2, FT>>>(dfeat, neighbor, out);
}